// round 16
// baseline (speedup 1.0000x reference)
#include <cuda_runtime.h>
#include <cuda_fp16.h>
#include <cstdint>

// Problem-fixed dims: B=4, S=2048 -> M=8192, D=2048, R=512.
#define MM 8192
#define DD 2048
#define RR 512

// Scratch (device globals; no allocation allowed in kernel_launch).
__device__ __half g_h[MM * (size_t)RR];     // stage-1 output fp16, [M][R]
__device__ __half g_win[(size_t)RR * DD];   // B^T for stage 1: [N=R][K=D]
__device__ __half g_wout[(size_t)DD * RR];  // B^T for stage 2: [N=D][K=R]

// software grid barrier state (generation counters: no per-replay reset races)
__device__ unsigned int g_cnt1 = 0;
__device__ unsigned int g_gen1 = 0;
__device__ unsigned int g_cnt2 = 0;
__device__ unsigned int g_gen2 = 0;
__device__ unsigned int g_ticket = 0;       // reset inside barrier #2 release

// ---------------------------------------------------------------------------
// helpers
// ---------------------------------------------------------------------------
__device__ __forceinline__ uint32_t smem_u32(const void* p) {
    return (uint32_t)__cvta_generic_to_shared(p);
}
__device__ __forceinline__ void cp_async16(uint32_t saddr, const void* gaddr) {
    asm volatile("cp.async.cg.shared.global [%0], [%1], 16;\n"
                 :: "r"(saddr), "l"(gaddr));
}
__device__ __forceinline__ void cp_commit() {
    asm volatile("cp.async.commit_group;\n");
}
template<int N>
__device__ __forceinline__ void cp_wait() {
    asm volatile("cp.async.wait_group %0;\n" :: "n"(N));
}
__device__ __forceinline__ void ldsm4(uint32_t* r, uint32_t addr) {
    asm volatile("ldmatrix.sync.aligned.m8n8.x4.shared.b16 {%0,%1,%2,%3}, [%4];\n"
                 : "=r"(r[0]), "=r"(r[1]), "=r"(r[2]), "=r"(r[3])
                 : "r"(addr));
}
__device__ __forceinline__ float2 lds_f2(uint32_t a) {
    float2 v;
    asm volatile("ld.shared.v2.f32 {%0,%1}, [%2];\n"
                 : "=f"(v.x), "=f"(v.y) : "r"(a));
    return v;
}
__device__ __forceinline__ void mma16816(float* c, const uint32_t* a, const uint32_t* b) {
    asm volatile(
        "mma.sync.aligned.m16n8k16.row.col.f32.f16.f16.f32 "
        "{%0,%1,%2,%3}, {%4,%5,%6,%7}, {%8,%9}, {%0,%1,%2,%3};\n"
        : "+f"(c[0]), "+f"(c[1]), "+f"(c[2]), "+f"(c[3])
        : "r"(a[0]), "r"(a[1]), "r"(a[2]), "r"(a[3]), "r"(b[0]), "r"(b[1]));
}

// ---------------------------------------------------------------------------
// soft-threshold helpers
// ---------------------------------------------------------------------------
__device__ __forceinline__ float second_smallest4(float a0, float a1, float a2, float a3) {
    float lo01 = fminf(a0, a1), hi01 = fmaxf(a0, a1);
    float lo23 = fminf(a2, a3), hi23 = fmaxf(a2, a3);
    return fminf(fmaxf(lo01, lo23), fminf(hi01, hi23));
}
__device__ __forceinline__ float shrink1(float w, float t, float s) {
    float a = fabsf(w) - t;
    a = a > 0.f ? a : 0.f;
    return copysignf(a, w) * s;
}
__device__ __forceinline__ uint16_t h16(float v) {
    __half h = __float2half_rn(v);
    return *(uint16_t*)&h;
}

// ---------------------------------------------------------------------------
// Persistent megakernel, grid = 256 CTAs x 128 threads, 2 CTAs/SM (all
// co-resident; same precondition as the round-15 proven barrier).
//   phase 1: win prep (slice per CTA) -> grid barrier #1
//   phase 2: stage-1 GEMM tile  h = fp16(x) @ win^T
//   phase 3: wout prep (slice per thread) -> grid barrier #2 (resets ticket)
//   phase 4: dynamic loop over 1024 stage-2 tiles: out = h @ wout^T + bias
// ---------------------------------------------------------------------------
__global__ __launch_bounds__(128, 2) void megakernel(
    const float* __restrict__ x,
    const float* __restrict__ w_in,  const float* __restrict__ s_in_p,
    const float* __restrict__ w_out, const float* __restrict__ s_out_p,
    const float* __restrict__ bias,  float* __restrict__ out)
{
    // stage-1 ring: A fp32 32KB + B fp16 16KB per stage, 2 stages = 96KB
    constexpr int A1BYTES = 128 * 256;
    constexpr int B1BYTES = 128 * 128;
    constexpr int STAGE1  = A1BYTES + B1BYTES;
    // stage-2 ring: A fp16 16KB + B fp16 16KB per stage, 3 stages = 96KB
    constexpr int A2BYTES = 128 * 128;
    constexpr int STAGE2  = 2 * A2BYTES;
    constexpr int RING    = 2 * STAGE1;    // == 3 * STAGE2 == 98304

    extern __shared__ __align__(1024) uint8_t dsmem[];
    const uint32_t rawS  = smem_u32(dsmem);
    const uint32_t sbase = (rawS + 1023u) & ~1023u;
    unsigned int* tslot  = (unsigned int*)(dsmem + (sbase - rawS) + RING);

    const int tid = threadIdx.x;
    const int wid = tid >> 5, ln = tid & 31;
    const int cid = blockIdx.y * (int)gridDim.x + blockIdx.x;   // 0..255
    const int bm = blockIdx.y * 128, bn = blockIdx.x * 128;
    const int warpM = (wid >> 1) * 64;
    const int warpN = (wid & 1) * 64;

    // ---------------- phase 1: win prep (d in [8*cid, 8*cid+8)) ------------
    {
        const int bd = cid * 8;
        uint64_t* sm64 = (uint64_t*)dsmem;          // 8KB scratch
        const float s = *s_in_p;
#pragma unroll
        for (int i = 0; i < 8; i++) {
            int l = tid + i * 128;
            int d  = l >> 7;
            int rg = l & 127;
            float4 wv = *(const float4*)(w_in + (size_t)(bd + d) * RR + rg * 4);
            float t = second_smallest4(fabsf(wv.x), fabsf(wv.y), fabsf(wv.z), fabsf(wv.w));
            uint64_t v = (uint64_t)h16(shrink1(wv.x, t, s))
                       | ((uint64_t)h16(shrink1(wv.y, t, s)) << 16)
                       | ((uint64_t)h16(shrink1(wv.z, t, s)) << 32)
                       | ((uint64_t)h16(shrink1(wv.w, t, s)) << 48);
            sm64[d * 128 + rg] = v;
        }
        __syncthreads();
        uint64_t u[8];
#pragma unroll
        for (int d = 0; d < 8; d++) u[d] = sm64[d * 128 + tid];
#pragma unroll
        for (int lane = 0; lane < 4; lane++) {
            int r = 4 * tid + lane;
            uint32_t o[4];
            uint16_t* oh = (uint16_t*)o;
            int sh = lane * 16;
#pragma unroll
            for (int d = 0; d < 8; d++) oh[d] = (uint16_t)(u[d] >> sh);
            *(uint4*)(g_win + (size_t)r * DD + (cid * 8)) = *(uint4*)o;
        }
        __threadfence();
        __syncthreads();
        if (tid == 0) {
            volatile unsigned int* vg = &g_gen1;
            unsigned int my_gen = *vg;
            unsigned int v = atomicAdd(&g_cnt1, 1);
            if (v == 255) {
                atomicExch(&g_cnt1, 0);
                __threadfence();
                atomicAdd(&g_gen1, 1);
            } else {
                while (*vg == my_gen) { }
            }
        }
        __syncthreads();
        __threadfence();
    }

    // ---------------- phase 2: stage-1 GEMM tile ----------------
    {
        float acc[4][8][4];
#pragma unroll
        for (int i = 0; i < 4; i++)
#pragma unroll
            for (int j = 0; j < 8; j++)
#pragma unroll
                for (int k = 0; k < 4; k++) acc[i][j][k] = 0.f;

        const int aSub = (ln & 1) * 8;
        const int kBit = (ln & 3) >> 1;
        uint32_t aHr[4];
#pragma unroll
        for (int mt = 0; mt < 4; mt++)
            aHr[mt] = (uint32_t)(2 * (warpM + mt * 16 + (ln >> 2)));

        const int mat = ln >> 3;
        const int mr  = ln & 7;
        const int bHi = mat & 1;
        uint32_t bRowOff[4]; int bRx[4];
#pragma unroll
        for (int np = 0; np < 4; np++) {
            int row = warpN + np * 16 + ((mat >> 1) << 3) + mr;
            bRowOff[np] = (uint32_t)(row * 128);
            bRx[np] = row & 7;
        }

        const int KT = DD >> 6;   // 32

        auto load_stage = [&](int kt, int s) {
            const uint32_t aS = sbase + (uint32_t)s * STAGE1;
            const uint32_t bS = aS + A1BYTES;
            const float*  Ag = x     + (size_t)bm * DD + (size_t)kt * 64;
            const __half* Bg = g_win + (size_t)bn * DD + (size_t)kt * 64;
#pragma unroll
            for (int i = 0; i < 16; i++) {
                int l = tid + i * 128;
                int hr = l >> 3, c = l & 7;
                uint32_t soff = (uint32_t)(hr * 128 + ((c ^ (hr & 7)) << 4));
                cp_async16(aS + soff, Ag + (size_t)(hr >> 1) * DD + (hr & 1) * 32 + c * 4);
            }
#pragma unroll
            for (int i = 0; i < 8; i++) {
                int l = tid + i * 128;
                int row = l >> 3, kc = l & 7;
                uint32_t soff = (uint32_t)(row * 128 + ((kc ^ (row & 7)) << 4));
                cp_async16(bS + soff, Bg + (size_t)row * DD + kc * 8);
            }
            cp_commit();
        };

        load_stage(0, 0);

        for (int kt = 0; kt < KT; kt++) {
            cp_wait<0>();
            __syncthreads();
            if (kt + 1 < KT) load_stage(kt + 1, (kt + 1) & 1);

            const uint32_t aS = sbase + (uint32_t)(kt & 1) * STAGE1;
            const uint32_t bS = aS + A1BYTES;
#pragma unroll
            for (int ks = 0; ks < 4; ks++) {
                const int hsel = ks >> 1;
                const int klo  = (ks & 1) * 4 + kBit;
                uint32_t af[4][4];
#pragma unroll
                for (int mt = 0; mt < 4; mt++) {
                    uint32_t hr0 = aHr[mt] + hsel;
                    uint32_t base0 = aS + hr0 * 128 + aSub;
                    uint32_t base1 = base0 + 16 * 128;
                    uint32_t x0 = (uint32_t)((klo ^ (hr0 & 7)) << 4);
                    uint32_t x2 = (uint32_t)(((klo + 2) ^ (hr0 & 7)) << 4);
                    float2 v0 = lds_f2(base0 + x0);
                    float2 v1 = lds_f2(base1 + x0);
                    float2 v2 = lds_f2(base0 + x2);
                    float2 v3 = lds_f2(base1 + x2);
                    __half2 h0 = __floats2half2_rn(v0.x, v0.y);
                    __half2 h1 = __floats2half2_rn(v1.x, v1.y);
                    __half2 h2 = __floats2half2_rn(v2.x, v2.y);
                    __half2 h3 = __floats2half2_rn(v3.x, v3.y);
                    af[mt][0] = *(uint32_t*)&h0;
                    af[mt][1] = *(uint32_t*)&h1;
                    af[mt][2] = *(uint32_t*)&h2;
                    af[mt][3] = *(uint32_t*)&h3;
                }
                uint32_t bf[8][2];
#pragma unroll
                for (int np = 0; np < 4; np++) {
                    uint32_t t[4];
                    ldsm4(t, bS + bRowOff[np] + (uint32_t)((((2 * ks + bHi) ^ bRx[np])) * 16));
                    bf[2 * np][0] = t[0]; bf[2 * np][1] = t[1];
                    bf[2 * np + 1][0] = t[2]; bf[2 * np + 1][1] = t[3];
                }
#pragma unroll
                for (int mt = 0; mt < 4; mt++)
#pragma unroll
                    for (int nt = 0; nt < 8; nt++)
                        mma16816(acc[mt][nt], af[mt], bf[nt]);
            }
        }

        // epilogue: h fp16
#pragma unroll
        for (int mt = 0; mt < 4; mt++) {
#pragma unroll
            for (int nt = 0; nt < 8; nt++) {
                int m0 = bm + warpM + mt * 16 + (ln >> 2);
                int n0 = bn + warpN + nt * 8 + (ln & 3) * 2;
                float* a = acc[mt][nt];
                __half2 v0 = __floats2half2_rn(a[0], a[1]);
                __half2 v1 = __floats2half2_rn(a[2], a[3]);
                *(__half2*)(g_h + (size_t)m0 * RR + n0)       = v0;
                *(__half2*)(g_h + (size_t)(m0 + 8) * RR + n0) = v1;
            }
        }
    }

    // ---------------- phase 3: wout prep + barrier #2 (ticket reset) -------
    {
        const int g  = cid * 128 + tid;   // 0..32767
        const int rb = g & 63;
        const int dg = g >> 6;
        const int r0 = rb * 8;
        const int d0 = dg * 4;
        const float s = *s_out_p;

        float w[4][8];
#pragma unroll
        for (int i = 0; i < 4; i++) {
            const float* p = w_out + (size_t)(d0 + i) * RR + r0;
            float4 u0 = *(const float4*)p;
            float4 u1 = *(const float4*)(p + 4);
            w[i][0] = u0.x; w[i][1] = u0.y; w[i][2] = u0.z; w[i][3] = u0.w;
            w[i][4] = u1.x; w[i][5] = u1.y; w[i][6] = u1.z; w[i][7] = u1.w;
        }
        uint16_t hh[4][8];
#pragma unroll
        for (int j = 0; j < 8; j++) {
            float t = second_smallest4(fabsf(w[0][j]), fabsf(w[1][j]),
                                       fabsf(w[2][j]), fabsf(w[3][j]));
#pragma unroll
            for (int i = 0; i < 4; i++)
                hh[i][j] = h16(shrink1(w[i][j], t, s));
        }
#pragma unroll
        for (int i = 0; i < 4; i++)
            *(uint4*)(g_wout + (size_t)(d0 + i) * RR + r0) = *(uint4*)hh[i];

        __threadfence();                 // covers g_h and g_wout writes
        __syncthreads();
        if (tid == 0) {
            volatile unsigned int* vg = &g_gen2;
            unsigned int my_gen = *vg;
            unsigned int v = atomicAdd(&g_cnt2, 1);
            if (v == 255) {
                atomicExch(&g_ticket, 0);    // reset queue while all wait
                atomicExch(&g_cnt2, 0);
                __threadfence();
                atomicAdd(&g_gen2, 1);
            } else {
                while (*vg == my_gen) { }
            }
        }
        __syncthreads();
        __threadfence();
    }

    // ---------------- phase 4: dynamic stage-2 tiles ----------------
    {
        const int mat = ln >> 3;
        const int mr  = ln & 7;
        const int aHi = mat >> 1;
        const int bHi = mat & 1;
        uint32_t aRowOff[4]; int aRx[4];
#pragma unroll
        for (int mt = 0; mt < 4; mt++) {
            int row = warpM + mt * 16 + ((mat & 1) << 3) + mr;
            aRowOff[mt] = (uint32_t)(row * 128);
            aRx[mt] = row & 7;
        }
        uint32_t bRowOff[4]; int bRx[4];
#pragma unroll
        for (int np = 0; np < 4; np++) {
            int row = warpN + np * 16 + ((mat >> 1) << 3) + mr;
            bRowOff[np] = (uint32_t)(row * 128);
            bRx[np] = row & 7;
        }

        const int KT = RR >> 6;   // 8

        for (;;) {
            if (tid == 0) *tslot = atomicAdd(&g_ticket, 1);
            __syncthreads();
            const unsigned int tk = *tslot;
            __syncthreads();
            if (tk >= 1024u) break;
            const int bm2 = (int)(tk >> 4) * 128;
            const int bn2 = (int)(tk & 15) * 128;

            float acc[4][8][4];
#pragma unroll
            for (int i = 0; i < 4; i++)
#pragma unroll
                for (int j = 0; j < 8; j++)
#pragma unroll
                    for (int k = 0; k < 4; k++) acc[i][j][k] = 0.f;

            auto load_stage = [&](int kt, int s) {
                const uint32_t aS = sbase + (uint32_t)s * STAGE2;
                const uint32_t bS = aS + A2BYTES;
                const __half* Ag = g_h    + (size_t)bm2 * RR + (size_t)kt * 64;
                const __half* Bg = g_wout + (size_t)bn2 * RR + (size_t)kt * 64;
#pragma unroll
                for (int i = 0; i < 8; i++) {
                    int l = tid + i * 128;
                    int row = l >> 3, kc = l & 7;
                    uint32_t soff = (uint32_t)(row * 128 + ((kc ^ (row & 7)) * 16));
                    cp_async16(aS + soff, Ag + (size_t)row * RR + kc * 8);
                    cp_async16(bS + soff, Bg + (size_t)row * RR + kc * 8);
                }
                cp_commit();
            };

            load_stage(0, 0);
            load_stage(1, 1);

            for (int kt = 0; kt < KT; kt++) {
                cp_wait<1>();
                __syncthreads();
                if (kt + 2 < KT) load_stage(kt + 2, (kt + 2) % 3);
                else cp_commit();

                const uint32_t aB = sbase + (uint32_t)(kt % 3) * STAGE2;
                const uint32_t bB = aB + A2BYTES;
#pragma unroll
                for (int ks = 0; ks < 4; ks++) {
                    uint32_t af[4][4];
#pragma unroll
                    for (int mt = 0; mt < 4; mt++)
                        ldsm4(af[mt], aB + aRowOff[mt] + (uint32_t)((((2 * ks + aHi) ^ aRx[mt])) * 16));
                    uint32_t bf[8][2];
#pragma unroll
                    for (int np = 0; np < 4; np++) {
                        uint32_t t[4];
                        ldsm4(t, bB + bRowOff[np] + (uint32_t)((((2 * ks + bHi) ^ bRx[np])) * 16));
                        bf[2 * np][0] = t[0]; bf[2 * np][1] = t[1];
                        bf[2 * np + 1][0] = t[2]; bf[2 * np + 1][1] = t[3];
                    }
#pragma unroll
                    for (int mt = 0; mt < 4; mt++)
#pragma unroll
                        for (int nt = 0; nt < 8; nt++)
                            mma16816(acc[mt][nt], af[mt], bf[nt]);
                }
            }

            // epilogue: fp32 + bias
#pragma unroll
            for (int mt = 0; mt < 4; mt++) {
#pragma unroll
                for (int nt = 0; nt < 8; nt++) {
                    int m0 = bm2 + warpM + mt * 16 + (ln >> 2);
                    int n0 = bn2 + warpN + nt * 8 + (ln & 3) * 2;
                    float* a = acc[mt][nt];
                    float b0 = bias[n0], b1 = bias[n0 + 1];
                    float2 v0 = make_float2(a[0] + b0, a[1] + b1);
                    float2 v1 = make_float2(a[2] + b0, a[3] + b1);
                    *(float2*)(out + (size_t)m0 * DD + n0)       = v0;
                    *(float2*)(out + (size_t)(m0 + 8) * DD + n0) = v1;
                }
            }
        }
    }
}

// ---------------------------------------------------------------------------
extern "C" void kernel_launch(void* const* d_in, const int* in_sizes, int n_in,
                              void* d_out, int out_size)
{
    const float* x    = (const float*)d_in[0];
    const float* w_in = (const float*)d_in[1];
    const float* w_out= (const float*)d_in[2];
    const float* bias = (const float*)d_in[3];
    const float* s_in = (const float*)d_in[4];
    const float* s_out= (const float*)d_in[5];
    float* out = (float*)d_out;

    // ring (98304) + align pad (1024) + ticket slot (32)
    constexpr int SMEM = 2 * (128 * 256 + 128 * 128) + 1024 + 32;

    cudaFuncSetAttribute(megakernel, cudaFuncAttributeMaxDynamicSharedMemorySize, SMEM);

    dim3 grid(RR / 128, MM / 128);   // (4, 64) = 256 CTAs, all co-resident
    megakernel<<<grid, 128, SMEM>>>(x, w_in, s_in, w_out, s_out, bias, out);
}

// round 17
// speedup vs baseline: 1.0487x; 1.0487x over previous
#include <cuda_runtime.h>
#include <cuda_fp16.h>
#include <cstdint>

// Problem-fixed dims: B=4, S=2048 -> M=8192, D=2048, R=512.
#define MM 8192
#define DD 2048
#define RR 512

// Scratch (device globals; no allocation allowed in kernel_launch).
__device__ __half g_h[MM * (size_t)RR];     // stage-1 output fp16, [M][R]
__device__ __half g_win[(size_t)RR * DD];   // B^T for stage 1: [N=R][K=D]
__device__ __half g_wout[(size_t)DD * RR];  // B^T for stage 2: [N=D][K=R]

// software grid barrier state (generation counter: no per-replay reset races)
__device__ unsigned int g_cnt = 0;
__device__ unsigned int g_gen = 0;

// ---------------------------------------------------------------------------
// helpers
// ---------------------------------------------------------------------------
__device__ __forceinline__ uint32_t smem_u32(const void* p) {
    return (uint32_t)__cvta_generic_to_shared(p);
}
__device__ __forceinline__ void cp_async16(uint32_t saddr, const void* gaddr) {
    asm volatile("cp.async.cg.shared.global [%0], [%1], 16;\n"
                 :: "r"(saddr), "l"(gaddr));
}
__device__ __forceinline__ void cp_commit() {
    asm volatile("cp.async.commit_group;\n");
}
template<int N>
__device__ __forceinline__ void cp_wait() {
    asm volatile("cp.async.wait_group %0;\n" :: "n"(N));
}
__device__ __forceinline__ void ldsm4(uint32_t* r, uint32_t addr) {
    asm volatile("ldmatrix.sync.aligned.m8n8.x4.shared.b16 {%0,%1,%2,%3}, [%4];\n"
                 : "=r"(r[0]), "=r"(r[1]), "=r"(r[2]), "=r"(r[3])
                 : "r"(addr));
}
__device__ __forceinline__ float2 lds_f2(uint32_t a) {
    float2 v;
    asm volatile("ld.shared.v2.f32 {%0,%1}, [%2];\n"
                 : "=f"(v.x), "=f"(v.y) : "r"(a));
    return v;
}
__device__ __forceinline__ void mma16816(float* c, const uint32_t* a, const uint32_t* b) {
    asm volatile(
        "mma.sync.aligned.m16n8k16.row.col.f32.f16.f16.f32 "
        "{%0,%1,%2,%3}, {%4,%5,%6,%7}, {%8,%9}, {%0,%1,%2,%3};\n"
        : "+f"(c[0]), "+f"(c[1]), "+f"(c[2]), "+f"(c[3])
        : "r"(a[0]), "r"(a[1]), "r"(a[2]), "r"(a[3]), "r"(b[0]), "r"(b[1]));
}

// ---------------------------------------------------------------------------
// soft-threshold helpers
// ---------------------------------------------------------------------------
__device__ __forceinline__ float second_smallest4(float a0, float a1, float a2, float a3) {
    float lo01 = fminf(a0, a1), hi01 = fmaxf(a0, a1);
    float lo23 = fminf(a2, a3), hi23 = fmaxf(a2, a3);
    return fminf(fmaxf(lo01, lo23), fminf(hi01, hi23));
}
__device__ __forceinline__ float shrink1(float w, float t, float s) {
    float a = fabsf(w) - t;
    a = a > 0.f ? a : 0.f;
    return copysignf(a, w) * s;
}
__device__ __forceinline__ uint16_t h16(float v) {
    __half h = __float2half_rn(v);
    return *(uint16_t*)&h;
}

// ---------------------------------------------------------------------------
// Stage 1: h[M][R] = fp16(x[M][D]) @ win^T.
// HEAD: stage-0 A (x) cp.async issued FIRST (independent of win), then each
//       CTA converts win d-slice [8*cid, 8*cid+8) via smem transpose, then a
//       software grid barrier (256 CTAs co-resident at 2/SM), then B of
//       stage 0 is loaded and the proven GEMM body runs.
// TAIL: fused wout prep (round-14 proven).
// ---------------------------------------------------------------------------
__global__ __launch_bounds__(128, 2) void gemm_s1(
    const float* __restrict__ A, const __half* __restrict__ Bt,
    __half* __restrict__ C, int K, int N,
    const float* __restrict__ w_in,  const float* __restrict__ s_in_p,
    const float* __restrict__ w_out, const float* __restrict__ s_out_p)
{
    constexpr int ABYTES = 128 * 256;      // 128 rows x 64 fp32
    constexpr int BBYTES = 128 * 128;      // 128 rows x 64 halves
    constexpr int STAGE  = ABYTES + BBYTES;

    extern __shared__ __align__(1024) uint8_t dsmem[];
    const uint32_t rawS  = smem_u32(dsmem);
    const uint32_t sbase = (rawS + 1023u) & ~1023u;

    const int tid = threadIdx.x;
    const int wid = tid >> 5, ln = tid & 31;
    const int bm = blockIdx.y * 128, bn = blockIdx.x * 128;
    const int warpM = (wid >> 1) * 64;
    const int warpN = (wid & 1) * 64;
    const int cid = blockIdx.y * (int)gridDim.x + blockIdx.x;   // 0..255

    auto load_A = [&](int kt, int s) {
        const uint32_t aS = sbase + (uint32_t)s * STAGE;
        const float* Ag = A + (size_t)bm * K + (size_t)kt * 64;
#pragma unroll
        for (int i = 0; i < 16; i++) {
            int l = tid + i * 128;
            int hr = l >> 3, c = l & 7;
            uint32_t soff = (uint32_t)(hr * 128 + ((c ^ (hr & 7)) << 4));
            cp_async16(aS + soff, Ag + (size_t)(hr >> 1) * K + (hr & 1) * 32 + c * 4);
        }
    };
    auto load_B = [&](int kt, int s) {
        const uint32_t bS = sbase + (uint32_t)s * STAGE + ABYTES;
        const __half* Bg = Bt + (size_t)bn * K + (size_t)kt * 64;
#pragma unroll
        for (int i = 0; i < 8; i++) {
            int l = tid + i * 128;
            int row = l >> 3, kc = l & 7;
            uint32_t soff = (uint32_t)(row * 128 + ((kc ^ (row & 7)) << 4));
            cp_async16(bS + soff, Bg + (size_t)row * K + kc * 8);
        }
    };

    // pre-issue stage-0 A tile: overlaps win prep + barrier with DRAM latency.
    // NOTE: smem ring does not overlap the prep scratch (prep uses a separate
    // carve at the END of the ring region? no -- it uses stage-1 B area which
    // IS written before barrier... so place prep scratch in stage-1 space at
    // sbase + STAGE (A of stage 1), which is untouched until load_stage(1).
    load_A(0, 0);
    cp_commit();

    // ---------------- win prep (slice d in [bd, bd+8), all r) --------------
    {
        const int bd = cid * 8;
        uint64_t* sm64 = (uint64_t*)(dsmem + (sbase - rawS) + STAGE);  // 8KB in stage-1 area
        const float s = *s_in_p;
#pragma unroll
        for (int i = 0; i < 8; i++) {
            int l = tid + i * 128;                  // 0..1023
            int d  = l >> 7;                        // 0..7
            int rg = l & 127;                       // 0..127
            float4 wv = *(const float4*)(w_in + (size_t)(bd + d) * RR + rg * 4);
            float t = second_smallest4(fabsf(wv.x), fabsf(wv.y), fabsf(wv.z), fabsf(wv.w));
            uint64_t v = (uint64_t)h16(shrink1(wv.x, t, s))
                       | ((uint64_t)h16(shrink1(wv.y, t, s)) << 16)
                       | ((uint64_t)h16(shrink1(wv.z, t, s)) << 32)
                       | ((uint64_t)h16(shrink1(wv.w, t, s)) << 48);
            sm64[d * 128 + rg] = v;
        }
        __syncthreads();
        uint64_t u[8];
#pragma unroll
        for (int d = 0; d < 8; d++) u[d] = sm64[d * 128 + tid];
#pragma unroll
        for (int lane = 0; lane < 4; lane++) {
            int r = 4 * tid + lane;
            uint32_t o[4];
            uint16_t* oh = (uint16_t*)o;
            int sh = lane * 16;
#pragma unroll
            for (int d = 0; d < 8; d++) oh[d] = (uint16_t)(u[d] >> sh);
            *(uint4*)(g_win + (size_t)r * DD + bd) = *(uint4*)o;
        }
        __threadfence();
        __syncthreads();                            // sm64 dead after this
        if (tid == 0) {
            volatile unsigned int* vg = &g_gen;
            unsigned int my_gen = *vg;
            unsigned int v = atomicAdd(&g_cnt, 1);
            if (v == 255) {
                atomicExch(&g_cnt, 0);
                __threadfence();
                atomicAdd(&g_gen, 1);
            } else {
                while (*vg == my_gen) { }
            }
        }
        __syncthreads();
        __threadfence();
    }

    // B of stage 0 (win now globally visible)
    load_B(0, 0);
    cp_commit();

    // ---------------- GEMM ----------------
    float acc[4][8][4];
#pragma unroll
    for (int i = 0; i < 4; i++)
#pragma unroll
        for (int j = 0; j < 8; j++)
#pragma unroll
            for (int k = 0; k < 4; k++) acc[i][j][k] = 0.f;

    const int aSub = (ln & 1) * 8;
    const int kBit = (ln & 3) >> 1;
    uint32_t aHr[4];
#pragma unroll
    for (int mt = 0; mt < 4; mt++)
        aHr[mt] = (uint32_t)(2 * (warpM + mt * 16 + (ln >> 2)));

    const int mat = ln >> 3;
    const int mr  = ln & 7;
    const int bHi = mat & 1;
    uint32_t bRowOff[4]; int bRx[4];
#pragma unroll
    for (int np = 0; np < 4; np++) {
        int row = warpN + np * 16 + ((mat >> 1) << 3) + mr;
        bRowOff[np] = (uint32_t)(row * 128);
        bRx[np] = row & 7;
    }

    const int KT = K >> 6;   // 32

    for (int kt = 0; kt < KT; kt++) {
        cp_wait<0>();
        __syncthreads();
        if (kt + 1 < KT) {
            load_A(kt + 1, (kt + 1) & 1);
            load_B(kt + 1, (kt + 1) & 1);
            cp_commit();
        }

        const uint32_t aS = sbase + (uint32_t)(kt & 1) * STAGE;
        const uint32_t bS = aS + ABYTES;
#pragma unroll
        for (int ks = 0; ks < 4; ks++) {
            const int hsel = ks >> 1;
            const int klo  = (ks & 1) * 4 + kBit;
            uint32_t af[4][4];
#pragma unroll
            for (int mt = 0; mt < 4; mt++) {
                uint32_t hr0 = aHr[mt] + hsel;
                uint32_t base0 = aS + hr0 * 128 + aSub;
                uint32_t base1 = base0 + 16 * 128;
                uint32_t x0 = (uint32_t)((klo ^ (hr0 & 7)) << 4);
                uint32_t x2 = (uint32_t)(((klo + 2) ^ (hr0 & 7)) << 4);
                float2 v0 = lds_f2(base0 + x0);
                float2 v1 = lds_f2(base1 + x0);
                float2 v2 = lds_f2(base0 + x2);
                float2 v3 = lds_f2(base1 + x2);
                __half2 h0 = __floats2half2_rn(v0.x, v0.y);
                __half2 h1 = __floats2half2_rn(v1.x, v1.y);
                __half2 h2 = __floats2half2_rn(v2.x, v2.y);
                __half2 h3 = __floats2half2_rn(v3.x, v3.y);
                af[mt][0] = *(uint32_t*)&h0;
                af[mt][1] = *(uint32_t*)&h1;
                af[mt][2] = *(uint32_t*)&h2;
                af[mt][3] = *(uint32_t*)&h3;
            }
            uint32_t bf[8][2];
#pragma unroll
            for (int np = 0; np < 4; np++) {
                uint32_t t[4];
                ldsm4(t, bS + bRowOff[np] + (uint32_t)((((2 * ks + bHi) ^ bRx[np])) * 16));
                bf[2 * np][0] = t[0]; bf[2 * np][1] = t[1];
                bf[2 * np + 1][0] = t[2]; bf[2 * np + 1][1] = t[3];
            }
#pragma unroll
            for (int mt = 0; mt < 4; mt++)
#pragma unroll
                for (int nt = 0; nt < 8; nt++)
                    mma16816(acc[mt][nt], af[mt], bf[nt]);
        }
    }

    // epilogue: h fp16
#pragma unroll
    for (int mt = 0; mt < 4; mt++) {
#pragma unroll
        for (int nt = 0; nt < 8; nt++) {
            int m0 = bm + warpM + mt * 16 + (ln >> 2);
            int n0 = bn + warpN + nt * 8 + (ln & 3) * 2;
            float* a = acc[mt][nt];
            __half2 v0 = __floats2half2_rn(a[0], a[1]);
            __half2 v1 = __floats2half2_rn(a[2], a[3]);
            *(__half2*)(C + (size_t)m0 * N + n0)       = v0;
            *(__half2*)(C + (size_t)(m0 + 8) * N + n0) = v1;
        }
    }

    // fused wout prep: thread g handles d-rows [d0,d0+4), r-cols [r0,r0+8).
    {
        const int g  = cid * 128 + tid;   // 0..32767
        const int rb = g & 63;
        const int dg = g >> 6;            // 0..511
        const int r0 = rb * 8;
        const int d0 = dg * 4;
        const float s = *s_out_p;

        float w[4][8];
#pragma unroll
        for (int i = 0; i < 4; i++) {
            const float* p = w_out + (size_t)(d0 + i) * RR + r0;
            float4 u0 = *(const float4*)p;
            float4 u1 = *(const float4*)(p + 4);
            w[i][0] = u0.x; w[i][1] = u0.y; w[i][2] = u0.z; w[i][3] = u0.w;
            w[i][4] = u1.x; w[i][5] = u1.y; w[i][6] = u1.z; w[i][7] = u1.w;
        }
        uint16_t hh[4][8];
#pragma unroll
        for (int j = 0; j < 8; j++) {
            float t = second_smallest4(fabsf(w[0][j]), fabsf(w[1][j]),
                                       fabsf(w[2][j]), fabsf(w[3][j]));
#pragma unroll
            for (int i = 0; i < 4; i++)
                hh[i][j] = h16(shrink1(w[i][j], t, s));
        }
#pragma unroll
        for (int i = 0; i < 4; i++)
            *(uint4*)(g_wout + (size_t)(d0 + i) * RR + r0) = *(uint4*)hh[i];
    }
}

// ---------------------------------------------------------------------------
// Stage 2: out[M][D] = h[M][R] @ wout^T + bias. fp16 in, fp32 out.
// BM=128, BN=128, BK=64, DEPTH=3, 128 threads, 2 CTAs/SM. (proven config)
// ---------------------------------------------------------------------------
__global__ __launch_bounds__(128, 2) void gemm_s2(
    const __half* __restrict__ A, const __half* __restrict__ Bt,
    float* __restrict__ C, const float* __restrict__ bias, int K, int N)
{
    constexpr int ABYTES = 128 * 128;
    constexpr int STAGE  = 2 * ABYTES;
    constexpr int DEPTH  = 3;

    extern __shared__ __align__(1024) uint8_t dsmem[];
    const uint32_t sbase = (smem_u32(dsmem) + 1023u) & ~1023u;

    const int tid = threadIdx.x;
    const int wid = tid >> 5, ln = tid & 31;
    const int bm = blockIdx.y * 128, bn = blockIdx.x * 128;
    const int warpM = (wid >> 1) * 64;
    const int warpN = (wid & 1) * 64;

    float acc[4][8][4];
#pragma unroll
    for (int i = 0; i < 4; i++)
#pragma unroll
        for (int j = 0; j < 8; j++)
#pragma unroll
            for (int k = 0; k < 4; k++) acc[i][j][k] = 0.f;

    const int mat = ln >> 3;
    const int mr  = ln & 7;
    const int aHi = mat >> 1;
    const int bHi = mat & 1;
    uint32_t aRowOff[4]; int aRx[4];
#pragma unroll
    for (int mt = 0; mt < 4; mt++) {
        int row = warpM + mt * 16 + ((mat & 1) << 3) + mr;
        aRowOff[mt] = (uint32_t)(row * 128);
        aRx[mt] = row & 7;
    }
    uint32_t bRowOff[4]; int bRx[4];
#pragma unroll
    for (int np = 0; np < 4; np++) {
        int row = warpN + np * 16 + ((mat >> 1) << 3) + mr;
        bRowOff[np] = (uint32_t)(row * 128);
        bRx[np] = row & 7;
    }

    const int KT = K >> 6;

    auto load_stage = [&](int kt, int s) {
        const uint32_t aS = sbase + (uint32_t)s * STAGE;
        const uint32_t bS = aS + ABYTES;
        const __half* Ag = A  + (size_t)bm * K + (size_t)kt * 64;
        const __half* Bg = Bt + (size_t)bn * K + (size_t)kt * 64;
#pragma unroll
        for (int i = 0; i < 8; i++) {
            int l = tid + i * 128;
            int row = l >> 3, kc = l & 7;
            uint32_t soff = (uint32_t)(row * 128 + ((kc ^ (row & 7)) * 16));
            cp_async16(aS + soff, Ag + (size_t)row * K + kc * 8);
            cp_async16(bS + soff, Bg + (size_t)row * K + kc * 8);
        }
        cp_commit();
    };

    load_stage(0, 0);
    load_stage(1, 1);

    for (int kt = 0; kt < KT; kt++) {
        cp_wait<1>();
        __syncthreads();
        if (kt + 2 < KT) load_stage(kt + 2, (kt + 2) % DEPTH);
        else cp_commit();

        const uint32_t aB = sbase + (uint32_t)(kt % DEPTH) * STAGE;
        const uint32_t bB = aB + ABYTES;
#pragma unroll
        for (int ks = 0; ks < 4; ks++) {
            uint32_t af[4][4];
#pragma unroll
            for (int mt = 0; mt < 4; mt++)
                ldsm4(af[mt], aB + aRowOff[mt] + (uint32_t)((((2 * ks + aHi) ^ aRx[mt])) * 16));
            uint32_t bf[8][2];
#pragma unroll
            for (int np = 0; np < 4; np++) {
                uint32_t t[4];
                ldsm4(t, bB + bRowOff[np] + (uint32_t)((((2 * ks + bHi) ^ bRx[np])) * 16));
                bf[2 * np][0] = t[0]; bf[2 * np][1] = t[1];
                bf[2 * np + 1][0] = t[2]; bf[2 * np + 1][1] = t[3];
            }
#pragma unroll
            for (int mt = 0; mt < 4; mt++)
#pragma unroll
                for (int nt = 0; nt < 8; nt++)
                    mma16816(acc[mt][nt], af[mt], bf[nt]);
        }
    }

    // epilogue: fp32 + bias
#pragma unroll
    for (int mt = 0; mt < 4; mt++) {
#pragma unroll
        for (int nt = 0; nt < 8; nt++) {
            int m0 = bm + warpM + mt * 16 + (ln >> 2);
            int n0 = bn + warpN + nt * 8 + (ln & 3) * 2;
            float* a = acc[mt][nt];
            float b0 = bias[n0], b1 = bias[n0 + 1];
            float2 v0 = make_float2(a[0] + b0, a[1] + b1);
            float2 v1 = make_float2(a[2] + b0, a[3] + b1);
            *(float2*)(C + (size_t)m0 * N + n0)       = v0;
            *(float2*)(C + (size_t)(m0 + 8) * N + n0) = v1;
        }
    }
}

// ---------------------------------------------------------------------------
extern "C" void kernel_launch(void* const* d_in, const int* in_sizes, int n_in,
                              void* d_out, int out_size)
{
    const float* x    = (const float*)d_in[0];
    const float* w_in = (const float*)d_in[1];
    const float* w_out= (const float*)d_in[2];
    const float* bias = (const float*)d_in[3];
    const float* s_in = (const float*)d_in[4];
    const float* s_out= (const float*)d_in[5];
    float* out = (float*)d_out;

    __half *h, *win, *wout;
    cudaGetSymbolAddress((void**)&h,    g_h);
    cudaGetSymbolAddress((void**)&win,  g_win);
    cudaGetSymbolAddress((void**)&wout, g_wout);

    constexpr int SMEM1 = 2 * (128 * 256 + 128 * 128) + 1024;  // 97KB
    constexpr int SMEM2 = 3 * (2 * 128 * 128) + 1024;          // 97KB

    cudaFuncSetAttribute(gemm_s1, cudaFuncAttributeMaxDynamicSharedMemorySize, SMEM1);
    cudaFuncSetAttribute(gemm_s2, cudaFuncAttributeMaxDynamicSharedMemorySize, SMEM2);

    // 1) stage 1 (+ in-kernel win prep w/ grid barrier, + fused wout prep):
    //    grid (4, 64) = 256 CTAs, all co-resident at 2 CTAs/SM.
    {
        dim3 grid(RR / 128, MM / 128);
        gemm_s1<<<grid, 128, SMEM1>>>(x, win, h, DD, RR, w_in, s_in, w_out, s_out);
    }
    // 2) stage 2: out = h @ wout^T + bias   grid (16, 64) = 1024 CTAs
    {
        dim3 grid(DD / 128, MM / 128);
        gemm_s2<<<grid, 128, SMEM2>>>(h, wout, out, bias, RR, DD);
    }
}